// round 12
// baseline (speedup 1.0000x reference)
#include <cuda_runtime.h>
#include <math.h>
#include <stdint.h>

// Problem constants
#define B_  256
#define S_  256
#define H_  512
#define H2_ 1024
#define O_  512

typedef unsigned long long ull;

// ---------------------------------------------------------------------------
// Scratch (device globals)
// ---------------------------------------------------------------------------
__device__ float g_xe  [(size_t)S_ * B_ * H_ ];
__device__ float g_Gx  [(size_t)S_ * B_ * H2_];
__device__ float g_Cx  [(size_t)S_ * B_ * H_ ];
__device__ float g_hall[(size_t)S_ * B_ * H_ ];
__device__ float g_h   [B_ * H_];
__device__ float g_z   [B_ * H_];

// pre-split bf16 hi/lo packed pairs: [row][col/2]
__device__ unsigned g_hh [B_ * H_ / 2];
__device__ unsigned g_hl [B_ * H_ / 2];
__device__ unsigned g_rhh[B_ * H_ / 2];
__device__ unsigned g_rhl[B_ * H_ / 2];

__device__ unsigned g_gcnt[8 * 32];   // group barrier counters (128B apart)

// ---------------------------------------------------------------------------
// helpers
// ---------------------------------------------------------------------------
__device__ __forceinline__ float sigm(float x) {
    return __fdividef(1.0f, 1.0f + __expf(-x));
}
__device__ __forceinline__ float tanh_fast(float x) {
    return 1.0f - 2.0f * __fdividef(1.0f, __expf(2.0f * x) + 1.0f);
}
__device__ __forceinline__ uint32_t smem_u32(const void* p) {
    uint32_t a;
    asm("{ .reg .u64 t; cvta.to.shared.u64 t, %1; cvt.u32.u64 %0, t; }"
        : "=r"(a) : "l"(p));
    return a;
}

// pack (f0,f1) -> bf16x2 hi word {lo=f0, hi=f1}; lo word = residuals
__device__ __forceinline__ void cvt_pair(float f0, float f1,
                                         unsigned& hi2, unsigned& lo2) {
    asm("cvt.rn.bf16x2.f32 %0, %2, %1;" : "=r"(hi2) : "f"(f0), "f"(f1));
    float h0 = __uint_as_float(hi2 << 16);
    float h1 = __uint_as_float(hi2 & 0xFFFF0000u);
    float l0 = f0 - h0, l1 = f1 - h1;
    asm("cvt.rn.bf16x2.f32 %0, %2, %1;" : "=r"(lo2) : "f"(l0), "f"(l1));
}

__device__ __forceinline__ void mma16816(float* c,
                                         unsigned a0, unsigned a1,
                                         unsigned a2, unsigned a3,
                                         unsigned b0, unsigned b1) {
    asm volatile(
        "mma.sync.aligned.m16n8k16.row.col.f32.bf16.bf16.f32 "
        "{%0,%1,%2,%3}, {%4,%5,%6,%7}, {%8,%9}, {%0,%1,%2,%3};"
        : "+f"(c[0]), "+f"(c[1]), "+f"(c[2]), "+f"(c[3])
        : "r"(a0), "r"(a1), "r"(a2), "r"(a3), "r"(b0), "r"(b1));
}

__device__ __forceinline__ void ldsm_x4(unsigned& r0, unsigned& r1,
                                        unsigned& r2, unsigned& r3,
                                        uint32_t addr) {
    asm volatile("ldmatrix.sync.aligned.m8n8.x4.shared.b16 {%0,%1,%2,%3}, [%4];"
                 : "=r"(r0), "=r"(r1), "=r"(r2), "=r"(r3) : "r"(addr));
}
__device__ __forceinline__ void ldsm_x2(unsigned& r0, unsigned& r1,
                                        uint32_t addr) {
    asm volatile("ldmatrix.sync.aligned.m8n8.x2.shared.b16 {%0,%1}, [%2];"
                 : "=r"(r0), "=r"(r1) : "r"(addr));
}

// ---------------------------------------------------------------------------
// Group barrier (16 blocks/group): REDG arrival + monotonic count wait
// ---------------------------------------------------------------------------
__device__ __forceinline__ void group_sync(int grp, unsigned target) {
    __threadfence();
    __syncthreads();
    if (threadIdx.x == 0) {
        unsigned* cp = &g_gcnt[grp * 32];
        asm volatile("red.global.gpu.add.u32 [%0], %1;"
                     :: "l"(cp), "r"(1u) : "memory");
        unsigned v;
        do {
            asm volatile("ld.acquire.gpu.u32 %0, [%1];" : "=r"(v) : "l"(cp));
        } while (v < target);
    }
    __syncthreads();
}

// ---------------------------------------------------------------------------
// Tensor-core big GEMM (proven R11, unchanged):
// C[65536, N] = A[65536,512] @ Bw[N,512]^T + bias
// ---------------------------------------------------------------------------
#define ASTR 48

__global__ __launch_bounds__(256, 2)
void sgemm_tc(int Asel, const float* __restrict__ Bw, int ldb,
              const float* __restrict__ bias, int mode,
              float* __restrict__ yout) {
    __shared__ char sAH[128 * ASTR];
    __shared__ char sAL[128 * ASTR];
    __shared__ char sBH[128 * ASTR];
    __shared__ char sBL[128 * ASTR];

    const int tid  = threadIdx.x;
    const int wid  = tid >> 5;
    const int lane = tid & 31;
    const int g    = lane >> 2;
    const int tg   = lane & 3;
    const int wm   = wid >> 1;
    const int wn   = wid & 1;
    const int m0   = blockIdx.y * 128;
    const int n0   = blockIdx.x * 128;

    const float* A = Asel ? g_hall : g_xe;
    const int lr = tid >> 1;
    const int lh = tid & 1;
    const float* Ap = A  + (size_t)(m0 + lr) * H_  + lh * 8;
    const float* Bp = Bw + (size_t)(n0 + lr) * ldb + lh * 8;

    float c[2][8][4];
    #pragma unroll
    for (int i = 0; i < 2; i++)
        #pragma unroll
        for (int j = 0; j < 8; j++)
            #pragma unroll
            for (int q = 0; q < 4; q++) c[i][j][q] = 0.f;

    float4 pa0 = *(const float4*)(Ap);
    float4 pa1 = *(const float4*)(Ap + 4);
    float4 pb0 = *(const float4*)(Bp);
    float4 pb1 = *(const float4*)(Bp + 4);

    #pragma unroll 1
    for (int k0 = 0; k0 < H_; k0 += 16) {
        {
            unsigned h0, l0, h1, l1, h2, l2, h3, l3;
            cvt_pair(pa0.x, pa0.y, h0, l0); cvt_pair(pa0.z, pa0.w, h1, l1);
            cvt_pair(pa1.x, pa1.y, h2, l2); cvt_pair(pa1.z, pa1.w, h3, l3);
            char* dA = (char*)(size_t)(lr * ASTR + lh * 16);
            *(uint2*)(sAH + (size_t)dA)     = make_uint2(h0, h1);
            *(uint2*)(sAH + (size_t)dA + 8) = make_uint2(h2, h3);
            *(uint2*)(sAL + (size_t)dA)     = make_uint2(l0, l1);
            *(uint2*)(sAL + (size_t)dA + 8) = make_uint2(l2, l3);
            cvt_pair(pb0.x, pb0.y, h0, l0); cvt_pair(pb0.z, pb0.w, h1, l1);
            cvt_pair(pb1.x, pb1.y, h2, l2); cvt_pair(pb1.z, pb1.w, h3, l3);
            *(uint2*)(sBH + (size_t)dA)     = make_uint2(h0, h1);
            *(uint2*)(sBH + (size_t)dA + 8) = make_uint2(h2, h3);
            *(uint2*)(sBL + (size_t)dA)     = make_uint2(l0, l1);
            *(uint2*)(sBL + (size_t)dA + 8) = make_uint2(l2, l3);
        }
        __syncthreads();
        if (k0 < H_ - 16) {
            pa0 = *(const float4*)(Ap + k0 + 16);
            pa1 = *(const float4*)(Ap + k0 + 20);
            pb0 = *(const float4*)(Bp + k0 + 16);
            pb1 = *(const float4*)(Bp + k0 + 20);
        }
        unsigned aH[2][4], aL[2][4];
        #pragma unroll
        for (int mt = 0; mt < 2; mt++) {
            int ab = (wm * 32 + mt * 16 + g) * ASTR + tg * 4;
            aH[mt][0] = *(const unsigned*)(sAH + ab);
            aH[mt][1] = *(const unsigned*)(sAH + ab + 8 * ASTR);
            aH[mt][2] = *(const unsigned*)(sAH + ab + 16);
            aH[mt][3] = *(const unsigned*)(sAH + ab + 8 * ASTR + 16);
            aL[mt][0] = *(const unsigned*)(sAL + ab);
            aL[mt][1] = *(const unsigned*)(sAL + ab + 8 * ASTR);
            aL[mt][2] = *(const unsigned*)(sAL + ab + 16);
            aL[mt][3] = *(const unsigned*)(sAL + ab + 8 * ASTR + 16);
        }
        #pragma unroll
        for (int nt2 = 0; nt2 < 8; nt2++) {
            int nb = (wn * 64 + nt2 * 8 + g) * ASTR + tg * 4;
            unsigned bh0 = *(const unsigned*)(sBH + nb);
            unsigned bh1 = *(const unsigned*)(sBH + nb + 16);
            unsigned bl0 = *(const unsigned*)(sBL + nb);
            unsigned bl1 = *(const unsigned*)(sBL + nb + 16);
            #pragma unroll
            for (int mt = 0; mt < 2; mt++) {
                mma16816(c[mt][nt2], aH[mt][0], aH[mt][1], aH[mt][2], aH[mt][3], bh0, bh1);
                mma16816(c[mt][nt2], aH[mt][0], aH[mt][1], aH[mt][2], aH[mt][3], bl0, bl1);
                mma16816(c[mt][nt2], aL[mt][0], aL[mt][1], aL[mt][2], aL[mt][3], bh0, bh1);
            }
        }
        __syncthreads();
    }

    #pragma unroll
    for (int mt = 0; mt < 2; mt++) {
        int row0 = m0 + wm * 32 + mt * 16 + g;
        int row1 = row0 + 8;
        #pragma unroll
        for (int nt2 = 0; nt2 < 8; nt2++) {
            int n = n0 + wn * 64 + nt2 * 8 + tg * 2;
            float2 bv = *(const float2*)(bias + n);
            float o00 = c[mt][nt2][0] + bv.x, o01 = c[mt][nt2][1] + bv.y;
            float o10 = c[mt][nt2][2] + bv.x, o11 = c[mt][nt2][3] + bv.y;
            if (mode == 0) {
                *(float2*)(g_Gx + (size_t)row0 * H2_ + n) = make_float2(o00, o01);
                *(float2*)(g_Gx + (size_t)row1 * H2_ + n) = make_float2(o10, o11);
            } else if (mode == 1) {
                *(float2*)(g_Cx + (size_t)row0 * H_ + n) = make_float2(o00, o01);
                *(float2*)(g_Cx + (size_t)row1 * H_ + n) = make_float2(o10, o11);
            } else {
                int s0 = row0 >> 8, b0i = row0 & 255;
                int s1 = row1 >> 8, b1i = row1 & 255;
                *(float2*)(yout + ((size_t)b0i * S_ + s0) * O_ + n) = make_float2(o00, o01);
                *(float2*)(yout + ((size_t)b1i * S_ + s1) * O_ + n) = make_float2(o10, o11);
            }
        }
    }
}

// ---------------------------------------------------------------------------
// Persistent recurrent kernel: ldmatrix fragments + pre-split bf16 state.
// 128 blocks x 256 threads (8 warps), group-of-16 barriers.
//   gate: m [mt*32,+32) x n [nt*64,+64) of 1024; warp = m16 x n16
//   cand: m [mt*32,+32) x n [nt*32,+32) of 512;  warp = m16 x n8
// Weights pre-split bf16 hi/lo in smem [n][k] (WROW=1040 B).
// A panels filled from pre-split globals (g_hh/g_hl, g_rhh/g_rhl) by pure
// uint4 LDG -> STS.128; epilogues produce the splits.
// ---------------------------------------------------------------------------
#define WROW 1040
#define AROW 272
#define SM_WGH 0
#define SM_WGL (SM_WGH + 64 * WROW)
#define SM_WHH (SM_WGL + 64 * WROW)
#define SM_WHL (SM_WHH + 32 * WROW)
#define SM_AH  (SM_WHL + 32 * WROW)
#define SM_AL  (SM_AH + 32 * AROW)
#define GRU_SMEM (SM_AL + 32 * AROW)    // 217088 bytes

__global__ __launch_bounds__(256, 1)
void gru_persist(const float* __restrict__ Wg, const float* __restrict__ Wh) {
    extern __shared__ char smc[];
    const uint32_t sbase = smem_u32(smc);

    const int tid  = threadIdx.x;
    const int bid  = blockIdx.x;
    const int mt   = bid >> 4;
    const int nt   = bid & 15;
    const int wid  = tid >> 5;
    const int lane = tid & 31;
    const int wm   = wid >> 2;
    const int wn   = wid & 3;
    const int g    = lane >> 2;
    const int tg   = lane & 3;

    // zero fp32 h + bf16 split h
    {
        int base = (bid * 256 + tid) * 4;
        *(float4*)&g_h[base] = make_float4(0.f, 0.f, 0.f, 0.f);
        int gid = bid * 256 + tid;
        *(uint2*)&g_hh[gid * 2] = make_uint2(0u, 0u);
        *(uint2*)&g_hl[gid * 2] = make_uint2(0u, 0u);
    }

    {   // Wg split: 64 rows (nt*64+j), k in [512,1024)
        int j  = tid >> 2;
        int ks = (tid & 3) * 128;
        const float* src = Wg + (size_t)(nt * 64 + j) * H2_ + H_ + ks;
        char* dh = smc + SM_WGH + j * WROW + ks * 2;
        char* dl = smc + SM_WGL + j * WROW + ks * 2;
        #pragma unroll 8
        for (int q = 0; q < 32; q++) {
            float4 v = *(const float4*)(src + q * 4);
            unsigned h0, l0, h1, l1;
            cvt_pair(v.x, v.y, h0, l0);
            cvt_pair(v.z, v.w, h1, l1);
            *(uint2*)(dh + q * 8) = make_uint2(h0, h1);
            *(uint2*)(dl + q * 8) = make_uint2(l0, l1);
        }
    }
    {   // Wh split: 32 rows (nt*32+j), k in [512,1024)
        int j  = tid >> 3;
        int ks = (tid & 7) * 64;
        const float* src = Wh + (size_t)(nt * 32 + j) * H2_ + H_ + ks;
        char* dh = smc + SM_WHH + j * WROW + ks * 2;
        char* dl = smc + SM_WHL + j * WROW + ks * 2;
        #pragma unroll 8
        for (int q = 0; q < 16; q++) {
            float4 v = *(const float4*)(src + q * 4);
            unsigned h0, l0, h1, l1;
            cvt_pair(v.x, v.y, h0, l0);
            cvt_pair(v.z, v.w, h1, l1);
            *(uint2*)(dh + q * 8) = make_uint2(h0, h1);
            *(uint2*)(dl + q * 8) = make_uint2(l0, l1);
        }
    }
    unsigned tgt = 0;
    group_sync(mt, tgt += 16);

    // panel-fill coords (row = lane -> conflict-free STS.128 phases)
    const int pr = tid & 31;             // row 0..31
    const int pq = tid >> 5;             // k-eighth 0..7
    const unsigned* hhrow  = g_hh  + (size_t)(mt * 32 + pr) * 256 + pq * 8;
    const unsigned* hlrow  = g_hl  + (size_t)(mt * 32 + pr) * 256 + pq * 8;
    const unsigned* rhhrow = g_rhh + (size_t)(mt * 32 + pr) * 256 + pq * 8;
    const unsigned* rhlrow = g_rhl + (size_t)(mt * 32 + pr) * 256 + pq * 8;
    char* stsH = smc + SM_AH + pr * AROW + pq * 32;
    char* stsL = smc + SM_AL + pr * AROW + pq * 32;

    // ldmatrix addresses
    const int arow  = wm * 16 + (lane & 7) + ((lane & 8) ? 8 : 0);
    const int akh   = (lane & 16) ? 16 : 0;
    const uint32_t aAH = sbase + SM_AH + arow * AROW + akh;
    const uint32_t aAL = sbase + SM_AL + arow * AROW + akh;
    const int bgrow = wn * 16 + (lane & 7) + ((lane & 16) ? 8 : 0);
    const int bkh   = (lane & 8) ? 16 : 0;
    const uint32_t aBgH = sbase + SM_WGH + bgrow * WROW + bkh;
    const uint32_t aBgL = sbase + SM_WGL + bgrow * WROW + bkh;
    const int bcrow = wn * 8 + (lane & 7);
    const uint32_t aBcH = sbase + SM_WHH + bcrow * WROW + bkh;
    const uint32_t aBcL = sbase + SM_WHL + bcrow * WROW + bkh;

    const int r0 = mt * 32 + wm * 16 + g;

    for (int t = 0; t < S_; t++) {
        // ===================== GATE PHASE =====================
        float cg0[4] = {0.f, 0.f, 0.f, 0.f};
        float cg1[4] = {0.f, 0.f, 0.f, 0.f};
        uint4 ph0 = __ldcg((const uint4*)(hhrow));
        uint4 ph1 = __ldcg((const uint4*)(hhrow + 4));
        uint4 pl0 = __ldcg((const uint4*)(hlrow));
        uint4 pl1 = __ldcg((const uint4*)(hlrow + 4));

        #pragma unroll 1
        for (int c = 0; c < 4; c++) {
            *(uint4*)(stsH)      = ph0;
            *(uint4*)(stsH + 16) = ph1;
            *(uint4*)(stsL)      = pl0;
            *(uint4*)(stsL + 16) = pl1;
            __syncthreads();
            if (c < 3) {
                ph0 = __ldcg((const uint4*)(hhrow + (c + 1) * 64));
                ph1 = __ldcg((const uint4*)(hhrow + (c + 1) * 64 + 4));
                pl0 = __ldcg((const uint4*)(hlrow + (c + 1) * 64));
                pl1 = __ldcg((const uint4*)(hlrow + (c + 1) * 64 + 4));
            }
            #pragma unroll
            for (int s = 0; s < 8; s++) {
                const int kw = c * 256 + s * 32;
                unsigned aH0, aH1, aH2, aH3, aL0, aL1, aL2, aL3;
                ldsm_x4(aH0, aH1, aH2, aH3, aAH + s * 32);
                ldsm_x4(aL0, aL1, aL2, aL3, aAL + s * 32);
                unsigned g0, g1, g2, g3, q0, q1, q2, q3;
                ldsm_x4(g0, g1, g2, g3, aBgH + kw);
                ldsm_x4(q0, q1, q2, q3, aBgL + kw);
                mma16816(cg0, aH0, aH1, aH2, aH3, g0, g1);
                mma16816(cg0, aH0, aH1, aH2, aH3, q0, q1);
                mma16816(cg0, aL0, aL1, aL2, aL3, g0, g1);
                mma16816(cg1, aH0, aH1, aH2, aH3, g2, g3);
                mma16816(cg1, aH0, aH1, aH2, aH3, q2, q3);
                mma16816(cg1, aL0, aL1, aL2, aL3, g2, g3);
            }
            if (c < 3) __syncthreads();
        }
        // gate epilogue
        {
            const float* Gxt = g_Gx + (size_t)t * B_ * H2_;
            #pragma unroll
            for (int tile = 0; tile < 2; tile++) {
                float* cc = tile ? cg1 : cg0;
                int n = nt * 64 + wn * 16 + tile * 8 + tg * 2;
                float2 gx0 = __ldcg((const float2*)(Gxt + (size_t)r0 * H2_ + n));
                float2 gx1 = __ldcg((const float2*)(Gxt + (size_t)(r0 + 8) * H2_ + n));
                float v00 = sigm(cc[0] + gx0.x), v01 = sigm(cc[1] + gx0.y);
                float v10 = sigm(cc[2] + gx1.x), v11 = sigm(cc[3] + gx1.y);
                if (nt < 8) {
                    __stcg((float2*)(g_z + r0 * H_ + n), make_float2(v00, v01));
                    __stcg((float2*)(g_z + (r0 + 8) * H_ + n), make_float2(v10, v11));
                } else {
                    int n2 = n - H_;
                    float2 hv0 = __ldcg((const float2*)(g_h + r0 * H_ + n2));
                    float2 hv1 = __ldcg((const float2*)(g_h + (r0 + 8) * H_ + n2));
                    unsigned hh, ll;
                    cvt_pair(v00 * hv0.x, v01 * hv0.y, hh, ll);
                    __stcg(&g_rhh[r0 * 256 + (n2 >> 1)], hh);
                    __stcg(&g_rhl[r0 * 256 + (n2 >> 1)], ll);
                    cvt_pair(v10 * hv1.x, v11 * hv1.y, hh, ll);
                    __stcg(&g_rhh[(r0 + 8) * 256 + (n2 >> 1)], hh);
                    __stcg(&g_rhl[(r0 + 8) * 256 + (n2 >> 1)], ll);
                }
            }
        }
        group_sync(mt, tgt += 16);

        // ===================== CANDIDATE PHASE =====================
        float cc[4] = {0.f, 0.f, 0.f, 0.f};
        ph0 = __ldcg((const uint4*)(rhhrow));
        ph1 = __ldcg((const uint4*)(rhhrow + 4));
        pl0 = __ldcg((const uint4*)(rhlrow));
        pl1 = __ldcg((const uint4*)(rhlrow + 4));

        #pragma unroll 1
        for (int c = 0; c < 4; c++) {
            *(uint4*)(stsH)      = ph0;
            *(uint4*)(stsH + 16) = ph1;
            *(uint4*)(stsL)      = pl0;
            *(uint4*)(stsL + 16) = pl1;
            __syncthreads();
            if (c < 3) {
                ph0 = __ldcg((const uint4*)(rhhrow + (c + 1) * 64));
                ph1 = __ldcg((const uint4*)(rhhrow + (c + 1) * 64 + 4));
                pl0 = __ldcg((const uint4*)(rhlrow + (c + 1) * 64));
                pl1 = __ldcg((const uint4*)(rhlrow + (c + 1) * 64 + 4));
            }
            #pragma unroll
            for (int s = 0; s < 8; s++) {
                const int kw = c * 256 + s * 32;
                unsigned aH0, aH1, aH2, aH3, aL0, aL1, aL2, aL3;
                ldsm_x4(aH0, aH1, aH2, aH3, aAH + s * 32);
                ldsm_x4(aL0, aL1, aL2, aL3, aAL + s * 32);
                unsigned bh0, bh1, bl0, bl1;
                ldsm_x2(bh0, bh1, aBcH + kw);
                ldsm_x2(bl0, bl1, aBcL + kw);
                mma16816(cc, aH0, aH1, aH2, aH3, bh0, bh1);
                mma16816(cc, aH0, aH1, aH2, aH3, bl0, bl1);
                mma16816(cc, aL0, aL1, aL2, aL3, bh0, bh1);
            }
            if (c < 3) __syncthreads();
        }
        // candidate epilogue: h update + split store
        {
            float* hall_t = g_hall + (size_t)t * B_ * H_;
            const float* Cxt = g_Cx + (size_t)t * B_ * H_;
            int n = nt * 32 + wn * 8 + tg * 2;
            #pragma unroll
            for (int rr = 0; rr < 2; rr++) {
                int r = r0 + rr * 8;
                size_t idx = (size_t)r * H_ + n;
                float2 cx = __ldcg((const float2*)(Cxt + idx));
                float2 zz = __ldcg((const float2*)(g_z + idx));
                float2 hh2 = __ldcg((const float2*)(g_h + idx));
                float c0 = tanh_fast(cc[rr * 2 + 0] + cx.x);
                float c1 = tanh_fast(cc[rr * 2 + 1] + cx.y);
                float2 hn = make_float2(fmaf(zz.x, c0 - hh2.x, hh2.x),
                                        fmaf(zz.y, c1 - hh2.y, hh2.y));
                __stcg((float2*)(g_h + idx), hn);
                __stcg((float2*)(hall_t + idx), hn);
                unsigned hw, lw;
                cvt_pair(hn.x, hn.y, hw, lw);
                __stcg(&g_hh[r * 256 + (n >> 1)], hw);
                __stcg(&g_hl[r * 256 + (n >> 1)], lw);
            }
        }
        group_sync(mt, tgt += 16);
    }
}

// ---------------------------------------------------------------------------
__global__ void gather_embed(const int* __restrict__ x,
                             const float* __restrict__ emb) {
    if (blockIdx.x == 0 && threadIdx.x < 8 * 32)
        g_gcnt[threadIdx.x] = 0;   // reset group-barrier counters each launch
    int idx = blockIdx.x * 256 + threadIdx.x;
    int h4  = idx & (H_ / 4 - 1);
    int row = idx >> 7;
    int b   = row & (B_ - 1);
    int s   = row >> 8;
    int tok = x[b * S_ + s];
    reinterpret_cast<float4*>(g_xe)[(size_t)row * (H_ / 4) + h4] =
        reinterpret_cast<const float4*>(emb)[(size_t)tok * (H_ / 4) + h4];
}

__global__ void copy_hfinal(float* __restrict__ out) {
    int i = blockIdx.x * 256 + threadIdx.x;
    out[i] = g_h[i];
}

// ---------------------------------------------------------------------------
extern "C" void kernel_launch(void* const* d_in, const int* in_sizes, int n_in,
                              void* d_out, int out_size) {
    (void)in_sizes; (void)n_in; (void)out_size;
    const int*   x   = (const int*)  d_in[0];
    const float* emb = (const float*)d_in[1];
    const float* Wg  = (const float*)d_in[2];
    const float* bg  = (const float*)d_in[3];
    const float* Wh  = (const float*)d_in[4];
    const float* bh  = (const float*)d_in[5];
    const float* Wo  = (const float*)d_in[6];
    const float* bo  = (const float*)d_in[7];
    float* out = (float*)d_out;

    static int smem_set = 0;
    if (!smem_set) {
        cudaFuncSetAttribute(gru_persist,
                             cudaFuncAttributeMaxDynamicSharedMemorySize,
                             GRU_SMEM);
        smem_set = 1;
    }

    gather_embed<<<(S_ * B_ * (H_ / 4)) / 256, 256>>>(x, emb);

    sgemm_tc<<<dim3(H2_ / 128, 65536 / 128), 256>>>(0, Wg, H2_, bg, 0, nullptr);
    sgemm_tc<<<dim3(H_  / 128, 65536 / 128), 256>>>(0, Wh, H2_, bh, 1, nullptr);

    gru_persist<<<128, 256, GRU_SMEM>>>(Wg, Wh);

    sgemm_tc<<<dim3(O_ / 128, 65536 / 128), 256>>>(1, Wo, H_, bo, 2,
                                                   out + (size_t)B_ * H_);
    copy_hfinal<<<(B_ * H_) / 256, 256>>>(out);
}

// round 13
// speedup vs baseline: 1.1584x; 1.1584x over previous
#include <cuda_runtime.h>
#include <math.h>
#include <stdint.h>

// Problem constants
#define B_  256
#define S_  256
#define H_  512
#define H2_ 1024
#define O_  512

typedef unsigned long long ull;

// ---------------------------------------------------------------------------
// Scratch (device globals)
// ---------------------------------------------------------------------------
__device__ float g_xe  [(size_t)S_ * B_ * H_ ];
__device__ float g_Gx  [(size_t)S_ * B_ * H2_];
__device__ float g_Cx  [(size_t)S_ * B_ * H_ ];
__device__ float g_hall[(size_t)S_ * B_ * H_ ];
__device__ float g_h   [B_ * H_];
__device__ float g_z   [B_ * H_];
__device__ float g_rh  [B_ * H_];

__device__ unsigned g_gcnt[8 * 32];   // group barrier counters (128B apart)

// ---------------------------------------------------------------------------
// helpers
// ---------------------------------------------------------------------------
__device__ __forceinline__ float sigm(float x) {
    return __fdividef(1.0f, 1.0f + __expf(-x));
}
__device__ __forceinline__ float tanh_fast(float x) {
    return 1.0f - 2.0f * __fdividef(1.0f, __expf(2.0f * x) + 1.0f);
}

// pack (f0,f1) -> bf16x2 hi word {lo=f0, hi=f1}; lo word = residuals
__device__ __forceinline__ void cvt_pair(float f0, float f1,
                                         unsigned& hi2, unsigned& lo2) {
    asm("cvt.rn.bf16x2.f32 %0, %2, %1;" : "=r"(hi2) : "f"(f0), "f"(f1));
    float h0 = __uint_as_float(hi2 << 16);
    float h1 = __uint_as_float(hi2 & 0xFFFF0000u);
    float l0 = f0 - h0, l1 = f1 - h1;
    asm("cvt.rn.bf16x2.f32 %0, %2, %1;" : "=r"(lo2) : "f"(l0), "f"(l1));
}

__device__ __forceinline__ void mma16816(float* c,
                                         unsigned a0, unsigned a1,
                                         unsigned a2, unsigned a3,
                                         unsigned b0, unsigned b1) {
    asm volatile(
        "mma.sync.aligned.m16n8k16.row.col.f32.bf16.bf16.f32 "
        "{%0,%1,%2,%3}, {%4,%5,%6,%7}, {%8,%9}, {%0,%1,%2,%3};"
        : "+f"(c[0]), "+f"(c[1]), "+f"(c[2]), "+f"(c[3])
        : "r"(a0), "r"(a1), "r"(a2), "r"(a3), "r"(b0), "r"(b1));
}

// ---------------------------------------------------------------------------
// Group barrier (32 blocks/group): REDG arrival + monotonic count wait
// ---------------------------------------------------------------------------
__device__ __forceinline__ void group_sync(int grp, unsigned target) {
    __threadfence();
    __syncthreads();
    if (threadIdx.x == 0) {
        unsigned* cp = &g_gcnt[grp * 32];
        asm volatile("red.global.gpu.add.u32 [%0], %1;"
                     :: "l"(cp), "r"(1u) : "memory");
        unsigned v;
        do {
            asm volatile("ld.acquire.gpu.u32 %0, [%1];" : "=r"(v) : "l"(cp));
        } while (v < target);
    }
    __syncthreads();
}

// ---------------------------------------------------------------------------
// Tensor-core big GEMM (proven R11, unchanged):
// C[65536, N] = A[65536,512] @ Bw[N,512]^T + bias
// ---------------------------------------------------------------------------
#define ASTR 48

__global__ __launch_bounds__(256, 2)
void sgemm_tc(int Asel, const float* __restrict__ Bw, int ldb,
              const float* __restrict__ bias, int mode,
              float* __restrict__ yout) {
    __shared__ char sAH[128 * ASTR];
    __shared__ char sAL[128 * ASTR];
    __shared__ char sBH[128 * ASTR];
    __shared__ char sBL[128 * ASTR];

    const int tid  = threadIdx.x;
    const int wid  = tid >> 5;
    const int lane = tid & 31;
    const int g    = lane >> 2;
    const int tg   = lane & 3;
    const int wm   = wid >> 1;
    const int wn   = wid & 1;
    const int m0   = blockIdx.y * 128;
    const int n0   = blockIdx.x * 128;

    const float* A = Asel ? g_hall : g_xe;
    const int lr = tid >> 1;
    const int lh = tid & 1;
    const float* Ap = A  + (size_t)(m0 + lr) * H_  + lh * 8;
    const float* Bp = Bw + (size_t)(n0 + lr) * ldb + lh * 8;

    float c[2][8][4];
    #pragma unroll
    for (int i = 0; i < 2; i++)
        #pragma unroll
        for (int j = 0; j < 8; j++)
            #pragma unroll
            for (int q = 0; q < 4; q++) c[i][j][q] = 0.f;

    float4 pa0 = *(const float4*)(Ap);
    float4 pa1 = *(const float4*)(Ap + 4);
    float4 pb0 = *(const float4*)(Bp);
    float4 pb1 = *(const float4*)(Bp + 4);

    #pragma unroll 1
    for (int k0 = 0; k0 < H_; k0 += 16) {
        {
            unsigned h0, l0, h1, l1, h2, l2, h3, l3;
            cvt_pair(pa0.x, pa0.y, h0, l0); cvt_pair(pa0.z, pa0.w, h1, l1);
            cvt_pair(pa1.x, pa1.y, h2, l2); cvt_pair(pa1.z, pa1.w, h3, l3);
            size_t dA = (size_t)(lr * ASTR + lh * 16);
            *(uint2*)(sAH + dA)     = make_uint2(h0, h1);
            *(uint2*)(sAH + dA + 8) = make_uint2(h2, h3);
            *(uint2*)(sAL + dA)     = make_uint2(l0, l1);
            *(uint2*)(sAL + dA + 8) = make_uint2(l2, l3);
            cvt_pair(pb0.x, pb0.y, h0, l0); cvt_pair(pb0.z, pb0.w, h1, l1);
            cvt_pair(pb1.x, pb1.y, h2, l2); cvt_pair(pb1.z, pb1.w, h3, l3);
            *(uint2*)(sBH + dA)     = make_uint2(h0, h1);
            *(uint2*)(sBH + dA + 8) = make_uint2(h2, h3);
            *(uint2*)(sBL + dA)     = make_uint2(l0, l1);
            *(uint2*)(sBL + dA + 8) = make_uint2(l2, l3);
        }
        __syncthreads();
        if (k0 < H_ - 16) {
            pa0 = *(const float4*)(Ap + k0 + 16);
            pa1 = *(const float4*)(Ap + k0 + 20);
            pb0 = *(const float4*)(Bp + k0 + 16);
            pb1 = *(const float4*)(Bp + k0 + 20);
        }
        unsigned aH[2][4], aL[2][4];
        #pragma unroll
        for (int mt = 0; mt < 2; mt++) {
            int ab = (wm * 32 + mt * 16 + g) * ASTR + tg * 4;
            aH[mt][0] = *(const unsigned*)(sAH + ab);
            aH[mt][1] = *(const unsigned*)(sAH + ab + 8 * ASTR);
            aH[mt][2] = *(const unsigned*)(sAH + ab + 16);
            aH[mt][3] = *(const unsigned*)(sAH + ab + 8 * ASTR + 16);
            aL[mt][0] = *(const unsigned*)(sAL + ab);
            aL[mt][1] = *(const unsigned*)(sAL + ab + 8 * ASTR);
            aL[mt][2] = *(const unsigned*)(sAL + ab + 16);
            aL[mt][3] = *(const unsigned*)(sAL + ab + 8 * ASTR + 16);
        }
        #pragma unroll
        for (int nt2 = 0; nt2 < 8; nt2++) {
            int nb = (wn * 64 + nt2 * 8 + g) * ASTR + tg * 4;
            unsigned bh0 = *(const unsigned*)(sBH + nb);
            unsigned bh1 = *(const unsigned*)(sBH + nb + 16);
            unsigned bl0 = *(const unsigned*)(sBL + nb);
            unsigned bl1 = *(const unsigned*)(sBL + nb + 16);
            #pragma unroll
            for (int mt = 0; mt < 2; mt++) {
                mma16816(c[mt][nt2], aH[mt][0], aH[mt][1], aH[mt][2], aH[mt][3], bh0, bh1);
                mma16816(c[mt][nt2], aH[mt][0], aH[mt][1], aH[mt][2], aH[mt][3], bl0, bl1);
                mma16816(c[mt][nt2], aL[mt][0], aL[mt][1], aL[mt][2], aL[mt][3], bh0, bh1);
            }
        }
        __syncthreads();
    }

    #pragma unroll
    for (int mt = 0; mt < 2; mt++) {
        int row0 = m0 + wm * 32 + mt * 16 + g;
        int row1 = row0 + 8;
        #pragma unroll
        for (int nt2 = 0; nt2 < 8; nt2++) {
            int n = n0 + wn * 64 + nt2 * 8 + tg * 2;
            float2 bv = *(const float2*)(bias + n);
            float o00 = c[mt][nt2][0] + bv.x, o01 = c[mt][nt2][1] + bv.y;
            float o10 = c[mt][nt2][2] + bv.x, o11 = c[mt][nt2][3] + bv.y;
            if (mode == 0) {
                *(float2*)(g_Gx + (size_t)row0 * H2_ + n) = make_float2(o00, o01);
                *(float2*)(g_Gx + (size_t)row1 * H2_ + n) = make_float2(o10, o11);
            } else if (mode == 1) {
                *(float2*)(g_Cx + (size_t)row0 * H_ + n) = make_float2(o00, o01);
                *(float2*)(g_Cx + (size_t)row1 * H_ + n) = make_float2(o10, o11);
            } else {
                int s0 = row0 >> 8, b0i = row0 & 255;
                int s1 = row1 >> 8, b1i = row1 & 255;
                *(float2*)(yout + ((size_t)b0i * S_ + s0) * O_ + n) = make_float2(o00, o01);
                *(float2*)(yout + ((size_t)b1i * S_ + s1) * O_ + n) = make_float2(o10, o11);
            }
        }
    }
}

// ---------------------------------------------------------------------------
// Persistent recurrent kernel: R11 engine, 2-CTA/SM geometry.
// 256 blocks x 256 threads (8 warps). Block (mt=bid>>5, nt=bid&31):
//   gate: m [mt*32,+32) x n [nt*32,+32) of 1024; warp (wm,wn) = m16 x n8
//   cand: m [mt*32,+32) x n [nt*16,+16) of 512;  warps wn<2 active
// Weights bf16 hi/lo in smem [n][k], WROW=1040 B (conflict-free fragments).
// A panel: 64-k chunks, AROW=144 B (36 words = 4 mod 32, conflict-free).
// Split-3: aH*bH (accA) + aH*bL + aL*bH (accB); c = accA+accB.
// ---------------------------------------------------------------------------
#define WROW 1040
#define AROW 144
#define SM_WGH 0
#define SM_WGL (SM_WGH + 32 * WROW)     // 33280
#define SM_WHH (SM_WGL + 32 * WROW)     // 66560
#define SM_WHL (SM_WHH + 16 * WROW)     // 83200
#define SM_AH  (SM_WHL + 16 * WROW)     // 99840
#define SM_AL  (SM_AH + 32 * AROW)      // 104448
#define GRU_SMEM (SM_AL + 32 * AROW)    // 109056 bytes (2 CTAs/SM fit)

__global__ __launch_bounds__(256, 2)
void gru_persist(const float* __restrict__ Wg, const float* __restrict__ Wh) {
    extern __shared__ char smc[];

    const int tid  = threadIdx.x;
    const int bid  = blockIdx.x;       // 0..255
    const int mt   = bid >> 5;         // 0..7
    const int nt   = bid & 31;         // 0..31
    const int wid  = tid >> 5;
    const int lane = tid & 31;
    const int wm   = wid >> 2;         // 0..1
    const int wn   = wid & 3;          // 0..3
    const int g    = lane >> 2;        // 0..7
    const int tg   = lane & 3;         // 0..3

    // zero h: 65536 threads x 2 floats
    {
        int gid = bid * 256 + tid;
        *(float2*)&g_h[gid * 2] = make_float2(0.f, 0.f);
    }

    {   // Wg slice: 32 rows (nt*32+j), k in [512,1024)
        int j  = tid >> 3;                  // 0..31
        int ks = (tid & 7) * 64;            // floats
        const float* src = Wg + (size_t)(nt * 32 + j) * H2_ + H_ + ks;
        char* dh = smc + SM_WGH + j * WROW + ks * 2;
        char* dl = smc + SM_WGL + j * WROW + ks * 2;
        #pragma unroll 8
        for (int q = 0; q < 16; q++) {
            float4 v = *(const float4*)(src + q * 4);
            unsigned h0, l0, h1, l1;
            cvt_pair(v.x, v.y, h0, l0);
            cvt_pair(v.z, v.w, h1, l1);
            *(uint2*)(dh + q * 8) = make_uint2(h0, h1);
            *(uint2*)(dl + q * 8) = make_uint2(l0, l1);
        }
    }
    {   // Wh slice: 16 rows (nt*16+j), k in [512,1024)
        int j  = tid >> 4;                  // 0..15
        int ks = (tid & 15) * 32;           // floats
        const float* src = Wh + (size_t)(nt * 16 + j) * H2_ + H_ + ks;
        char* dh = smc + SM_WHH + j * WROW + ks * 2;
        char* dl = smc + SM_WHL + j * WROW + ks * 2;
        #pragma unroll 8
        for (int q = 0; q < 8; q++) {
            float4 v = *(const float4*)(src + q * 4);
            unsigned h0, l0, h1, l1;
            cvt_pair(v.x, v.y, h0, l0);
            cvt_pair(v.z, v.w, h1, l1);
            *(uint2*)(dh + q * 8) = make_uint2(h0, h1);
            *(uint2*)(dl + q * 8) = make_uint2(l0, l1);
        }
    }
    unsigned tgt = 0;
    group_sync(mt, tgt += 32);

    const float* hrow  = g_h  + (size_t)mt * 32 * H_;
    const float* rhrow = g_rh + (size_t)mt * 32 * H_;

    // panel-fill coords: row pr (0..31), k-seg pseg*8 floats within 64-k chunk
    const int pr   = tid >> 3;
    const int pseg = tid & 7;
    char* stsH = smc + SM_AH + pr * AROW + pseg * 16;
    char* stsL = smc + SM_AL + pr * AROW + pseg * 16;

    // fragment bases
    const int aHb = SM_AH + (wm * 16 + g) * AROW + tg * 4;
    const int aLb = SM_AL + (wm * 16 + g) * AROW + tg * 4;
    const int bgH = SM_WGH + (wn * 8 + g) * WROW + tg * 4;
    const int bgL = SM_WGL + (wn * 8 + g) * WROW + tg * 4;
    const int bhH = SM_WHH + ((wn & 1) * 8 + g) * WROW + tg * 4;
    const int bhL = SM_WHL + ((wn & 1) * 8 + g) * WROW + tg * 4;

    const int r0 = mt * 32 + wm * 16 + g;     // output rows r0, r0+8
    const int ngt = nt * 32 + wn * 8 + tg * 2;  // gate col (of 1024)
    const int nct = nt * 16 + wn * 8 + tg * 2;  // cand col (of 512), wn<2

    for (int t = 0; t < S_; t++) {
        // ===================== GATE PHASE =====================
        float cA[4] = {0.f, 0.f, 0.f, 0.f};
        float cB[4] = {0.f, 0.f, 0.f, 0.f};
        float4 pf0 = __ldcg((const float4*)(hrow + (size_t)pr * H_ + pseg * 8));
        float4 pf1 = __ldcg((const float4*)(hrow + (size_t)pr * H_ + pseg * 8 + 4));
        const float* Gxt = g_Gx + (size_t)t * B_ * H2_;
        float2 gx0 = __ldcg((const float2*)(Gxt + (size_t)r0 * H2_ + ngt));
        float2 gx1 = __ldcg((const float2*)(Gxt + (size_t)(r0 + 8) * H2_ + ngt));
        float2 hv0 = make_float2(0.f, 0.f), hv1 = hv0;
        if (nt >= 16) {
            int n2 = ngt - H_;
            hv0 = __ldcg((const float2*)(g_h + r0 * H_ + n2));
            hv1 = __ldcg((const float2*)(g_h + (r0 + 8) * H_ + n2));
        }

        #pragma unroll 1
        for (int c = 0; c < 8; c++) {
            {
                unsigned h0, l0, h1, l1, h2, l2, h3, l3;
                cvt_pair(pf0.x, pf0.y, h0, l0); cvt_pair(pf0.z, pf0.w, h1, l1);
                cvt_pair(pf1.x, pf1.y, h2, l2); cvt_pair(pf1.z, pf1.w, h3, l3);
                *(uint4*)(stsH) = make_uint4(h0, h1, h2, h3);
                *(uint4*)(stsL) = make_uint4(l0, l1, l2, l3);
            }
            __syncthreads();
            if (c < 7) {
                int ko = (c + 1) * 64 + pseg * 8;
                pf0 = __ldcg((const float4*)(hrow + (size_t)pr * H_ + ko));
                pf1 = __ldcg((const float4*)(hrow + (size_t)pr * H_ + ko + 4));
            }
            const int kwb = c * 128;
            #pragma unroll
            for (int s = 0; s < 4; s++) {
                const int ka = s * 32;
                const int kw = kwb + s * 32;
                unsigned aH0 = *(const unsigned*)(smc + aHb + ka);
                unsigned aH1 = *(const unsigned*)(smc + aHb + 8 * AROW + ka);
                unsigned aH2 = *(const unsigned*)(smc + aHb + ka + 16);
                unsigned aH3 = *(const unsigned*)(smc + aHb + 8 * AROW + ka + 16);
                unsigned aL0 = *(const unsigned*)(smc + aLb + ka);
                unsigned aL1 = *(const unsigned*)(smc + aLb + 8 * AROW + ka);
                unsigned aL2 = *(const unsigned*)(smc + aLb + ka + 16);
                unsigned aL3 = *(const unsigned*)(smc + aLb + 8 * AROW + ka + 16);
                unsigned bh0 = *(const unsigned*)(smc + bgH + kw);
                unsigned bh1 = *(const unsigned*)(smc + bgH + kw + 16);
                unsigned bl0 = *(const unsigned*)(smc + bgL + kw);
                unsigned bl1 = *(const unsigned*)(smc + bgL + kw + 16);
                mma16816(cA, aH0, aH1, aH2, aH3, bh0, bh1);
                mma16816(cB, aH0, aH1, aH2, aH3, bl0, bl1);
                mma16816(cB, aL0, aL1, aL2, aL3, bh0, bh1);
            }
            if (c < 7) __syncthreads();
        }
        // gate epilogue (m16n8: c0,c1 -> row r0; c2,c3 -> row r0+8)
        {
            float v00 = sigm(cA[0] + cB[0] + gx0.x);
            float v01 = sigm(cA[1] + cB[1] + gx0.y);
            float v10 = sigm(cA[2] + cB[2] + gx1.x);
            float v11 = sigm(cA[3] + cB[3] + gx1.y);
            if (nt < 16) {
                __stcg((float2*)(g_z + r0 * H_ + ngt), make_float2(v00, v01));
                __stcg((float2*)(g_z + (r0 + 8) * H_ + ngt), make_float2(v10, v11));
            } else {
                int n2 = ngt - H_;
                __stcg((float2*)(g_rh + r0 * H_ + n2),
                       make_float2(v00 * hv0.x, v01 * hv0.y));
                __stcg((float2*)(g_rh + (r0 + 8) * H_ + n2),
                       make_float2(v10 * hv1.x, v11 * hv1.y));
            }
        }
        group_sync(mt, tgt += 32);

        // ===================== CANDIDATE PHASE =====================
        float dA[4] = {0.f, 0.f, 0.f, 0.f};
        float dB[4] = {0.f, 0.f, 0.f, 0.f};
        pf0 = __ldcg((const float4*)(rhrow + (size_t)pr * H_ + pseg * 8));
        pf1 = __ldcg((const float4*)(rhrow + (size_t)pr * H_ + pseg * 8 + 4));
        float2 cx0, cx1, zz0, zz1, hh0, hh1;
        if (wn < 2) {
            const float* Cxt = g_Cx + (size_t)t * B_ * H_;
            cx0 = __ldcg((const float2*)(Cxt + (size_t)r0 * H_ + nct));
            cx1 = __ldcg((const float2*)(Cxt + (size_t)(r0 + 8) * H_ + nct));
            zz0 = __ldcg((const float2*)(g_z + r0 * H_ + nct));
            zz1 = __ldcg((const float2*)(g_z + (r0 + 8) * H_ + nct));
            hh0 = __ldcg((const float2*)(g_h + r0 * H_ + nct));
            hh1 = __ldcg((const float2*)(g_h + (r0 + 8) * H_ + nct));
        }

        #pragma unroll 1
        for (int c = 0; c < 8; c++) {
            {
                unsigned h0, l0, h1, l1, h2, l2, h3, l3;
                cvt_pair(pf0.x, pf0.y, h0, l0); cvt_pair(pf0.z, pf0.w, h1, l1);
                cvt_pair(pf1.x, pf1.y, h2, l2); cvt_pair(pf1.z, pf1.w, h3, l3);
                *(uint4*)(stsH) = make_uint4(h0, h1, h2, h3);
                *(uint4*)(stsL) = make_uint4(l0, l1, l2, l3);
            }
            __syncthreads();
            if (c < 7) {
                int ko = (c + 1) * 64 + pseg * 8;
                pf0 = __ldcg((const float4*)(rhrow + (size_t)pr * H_ + ko));
                pf1 = __ldcg((const float4*)(rhrow + (size_t)pr * H_ + ko + 4));
            }
            if (wn < 2) {
                const int kwb = c * 128;
                #pragma unroll
                for (int s = 0; s < 4; s++) {
                    const int ka = s * 32;
                    const int kw = kwb + s * 32;
                    unsigned aH0 = *(const unsigned*)(smc + aHb + ka);
                    unsigned aH1 = *(const unsigned*)(smc + aHb + 8 * AROW + ka);
                    unsigned aH2 = *(const unsigned*)(smc + aHb + ka + 16);
                    unsigned aH3 = *(const unsigned*)(smc + aHb + 8 * AROW + ka + 16);
                    unsigned aL0 = *(const unsigned*)(smc + aLb + ka);
                    unsigned aL1 = *(const unsigned*)(smc + aLb + 8 * AROW + ka);
                    unsigned aL2 = *(const unsigned*)(smc + aLb + ka + 16);
                    unsigned aL3 = *(const unsigned*)(smc + aLb + 8 * AROW + ka + 16);
                    unsigned bh0 = *(const unsigned*)(smc + bhH + kw);
                    unsigned bh1 = *(const unsigned*)(smc + bhH + kw + 16);
                    unsigned bl0 = *(const unsigned*)(smc + bhL + kw);
                    unsigned bl1 = *(const unsigned*)(smc + bhL + kw + 16);
                    mma16816(dA, aH0, aH1, aH2, aH3, bh0, bh1);
                    mma16816(dB, aH0, aH1, aH2, aH3, bl0, bl1);
                    mma16816(dB, aL0, aL1, aL2, aL3, bh0, bh1);
                }
            }
            if (c < 7) __syncthreads();
        }
        // candidate epilogue: h update (active warps only)
        if (wn < 2) {
            float* hall_t = g_hall + (size_t)t * B_ * H_;
            float c00 = tanh_fast(dA[0] + dB[0] + cx0.x);
            float c01 = tanh_fast(dA[1] + dB[1] + cx0.y);
            float c10 = tanh_fast(dA[2] + dB[2] + cx1.x);
            float c11 = tanh_fast(dA[3] + dB[3] + cx1.y);
            float2 hn0 = make_float2(fmaf(zz0.x, c00 - hh0.x, hh0.x),
                                     fmaf(zz0.y, c01 - hh0.y, hh0.y));
            float2 hn1 = make_float2(fmaf(zz1.x, c10 - hh1.x, hh1.x),
                                     fmaf(zz1.y, c11 - hh1.y, hh1.y));
            __stcg((float2*)(g_h + r0 * H_ + nct), hn0);
            __stcg((float2*)(g_h + (r0 + 8) * H_ + nct), hn1);
            __stcg((float2*)(hall_t + (size_t)r0 * H_ + nct), hn0);
            __stcg((float2*)(hall_t + (size_t)(r0 + 8) * H_ + nct), hn1);
        }
        group_sync(mt, tgt += 32);
    }
}

// ---------------------------------------------------------------------------
__global__ void gather_embed(const int* __restrict__ x,
                             const float* __restrict__ emb) {
    if (blockIdx.x == 0 && threadIdx.x < 8 * 32)
        g_gcnt[threadIdx.x] = 0;   // reset group-barrier counters each launch
    int idx = blockIdx.x * 256 + threadIdx.x;
    int h4  = idx & (H_ / 4 - 1);
    int row = idx >> 7;
    int b   = row & (B_ - 1);
    int s   = row >> 8;
    int tok = x[b * S_ + s];
    reinterpret_cast<float4*>(g_xe)[(size_t)row * (H_ / 4) + h4] =
        reinterpret_cast<const float4*>(emb)[(size_t)tok * (H_ / 4) + h4];
}

__global__ void copy_hfinal(float* __restrict__ out) {
    int i = blockIdx.x * 256 + threadIdx.x;
    out[i] = g_h[i];
}

// ---------------------------------------------------------------------------
extern "C" void kernel_launch(void* const* d_in, const int* in_sizes, int n_in,
                              void* d_out, int out_size) {
    (void)in_sizes; (void)n_in; (void)out_size;
    const int*   x   = (const int*)  d_in[0];
    const float* emb = (const float*)d_in[1];
    const float* Wg  = (const float*)d_in[2];
    const float* bg  = (const float*)d_in[3];
    const float* Wh  = (const float*)d_in[4];
    const float* bh  = (const float*)d_in[5];
    const float* Wo  = (const float*)d_in[6];
    const float* bo  = (const float*)d_in[7];
    float* out = (float*)d_out;

    static int smem_set = 0;
    if (!smem_set) {
        cudaFuncSetAttribute(gru_persist,
                             cudaFuncAttributeMaxDynamicSharedMemorySize,
                             GRU_SMEM);
        smem_set = 1;
    }

    gather_embed<<<(S_ * B_ * (H_ / 4)) / 256, 256>>>(x, emb);

    sgemm_tc<<<dim3(H2_ / 128, 65536 / 128), 256>>>(0, Wg, H2_, bg, 0, nullptr);
    sgemm_tc<<<dim3(H_  / 128, 65536 / 128), 256>>>(0, Wh, H2_, bh, 1, nullptr);

    gru_persist<<<256, 256, GRU_SMEM>>>(Wg, Wh);

    sgemm_tc<<<dim3(O_ / 128, 65536 / 128), 256>>>(1, Wo, H_, bo, 2,
                                                   out + (size_t)B_ * H_);
    copy_hfinal<<<(B_ * H_) / 256, 256>>>(out);
}